// round 17
// baseline (speedup 1.0000x reference)
#include <cuda_runtime.h>
#include <cuda_bf16.h>
#include <stdint.h>
#include <math.h>

// Problem constants
#define BB 8
#define TT 2048
#define DD 1024
#define WW 16
#define HH 8
#define HDIM 128
#define NWIN (TT / WW)
#define MTOK (BB * TT)          // 16384
#define D4 (4 * DD)             // 4096
#define D3 (3 * DD)             // 3072

// tf32 GEMM tiling: CTA 128x256, 8 warps, warp tile 64x64, BK=32, 3-stage
#define BM 128
#define BN 256
#define BK 32
#define TRS 40                  // smem row stride in floats (32 + 8 pad)
#define SA_BYTES (BM * TRS * 4) // 20480
#define SB_BYTES (BN * TRS * 4) // 40960
#define STAGE (SA_BYTES + SB_BYTES)  // 61440
#define NSTAGE 3
#define TGSMEM (NSTAGE * STAGE)      // 184320 (1 CTA/SM)

// ---------------------------------------------------------------------------
// Scratch (__device__ globals; allocation-free)
// "t" buffers are tf32-rounded AND K-permuted (8-group slots
// [k0,k4,k1,k5,k2,k6,k3,k7]) for paired ld.shared.v2 fragment loads.
// ---------------------------------------------------------------------------
__device__ float g_x[MTOK * DD];        // exact x (residual)
__device__ float g_xt[MTOK * DD];       // tf32+perm x (QKV A)
__device__ float g_qkv[MTOK * D3];      // fp32 QKV (attention input)
__device__ float g_aot[MTOK * DD];      // tf32+perm attention out (out-proj A)
__device__ float g_proj[MTOK * DD];     // fp32 out-proj (residual)
__device__ float g_h[MTOK * DD];        // exact h (residual)
__device__ float g_ht[MTOK * DD];       // tf32+perm h (FFN1 A)
__device__ float g_f1t[MTOK * D4];      // tf32+perm gelu(FFN1) (FFN2 A)
__device__ float g_f2[MTOK * DD];       // fp32 FFN2 out
__device__ float g_wqkvt[D3 * DD];      // tf32+perm weights
__device__ float g_woutt[DD * DD];
__device__ float g_w1t[D4 * DD];
__device__ float g_w2t[DD * D4];

// ---------------------------------------------------------------------------
// Helpers
// ---------------------------------------------------------------------------
__device__ __forceinline__ uint32_t smem_u32(const void* p) {
    uint32_t a;
    asm("{ .reg .u64 t; cvta.to.shared.u64 t, %1; cvt.u32.u64 %0, t; }"
        : "=r"(a) : "l"(p));
    return a;
}
#define CP_ASYNC16(dst, src) \
    asm volatile("cp.async.cg.shared.global [%0], [%1], 16;" :: "r"(dst), "l"(src))
#define CP_COMMIT() asm volatile("cp.async.commit_group;" ::: "memory")
#define CP_WAIT1() asm volatile("cp.async.wait_group 1;" ::: "memory")
#define CP_WAIT0() asm volatile("cp.async.wait_group 0;" ::: "memory")
#define LDS64(r0, r1, addr) \
    asm volatile("ld.shared.v2.b32 {%0,%1}, [%2];" : "=r"(r0), "=r"(r1) : "r"(addr))
#define MMATF32(d, a0, a1, a2, a3, b0, b1) \
    asm volatile("mma.sync.aligned.m16n8k8.row.col.f32.tf32.tf32.f32 " \
                 "{%0,%1,%2,%3},{%4,%5,%6,%7},{%8,%9},{%0,%1,%2,%3};" \
                 : "+f"((d)[0]), "+f"((d)[1]), "+f"((d)[2]), "+f"((d)[3]) \
                 : "r"(a0), "r"(a1), "r"(a2), "r"(a3), "r"(b0), "r"(b1))

__device__ __forceinline__ float tf32r(float v) {
    float o;
    asm("cvt.rna.tf32.f32 %0, %1;" : "=f"(o) : "f"(v));
    return o;
}
__device__ __forceinline__ float gelu_exact(float v) {
    return v * 0.5f * (1.0f + erff(v * 0.7071067811865476f));
}
// K permutation within 8-groups: slot of original column c
__device__ __forceinline__ int kperm(int c) {
    return (c & ~7) | (((c & 3) << 1) | ((c & 7) >> 2));
}

// ---------------------------------------------------------------------------
// tf32 single-pass GEMM: C[m][n] = sum_k A[m][k]*B[n][k] + bias[n]
// A,B tf32-rounded + K-permuted. CTA 128x256, warp tile 64x64 (2x4 warp grid),
// 3-stage cp.async pipeline, one __syncthreads per chunk.
// mode 0: fp32 out. mode 1: gelu -> tf32-rounded, K-permuted fp32 out.
// ---------------------------------------------------------------------------
__global__ __launch_bounds__(256)
void gemm_tf32(const float* __restrict__ A, const float* __restrict__ Bm,
               const float* __restrict__ bias, float* __restrict__ Cf,
               int N, int K, int mode) {
    extern __shared__ char smem[];
    const uint32_t sbase = smem_u32(smem);
    const int tid = threadIdx.x;
    const int w = tid >> 5;
    const int lane = tid & 31;
    const int warp_m = (w >> 2) * 64;   // 0 or 64
    const int warp_n = (w & 3) * 64;    // 0,64,128,192
    const int bm = blockIdx.y * BM;
    const int bn = blockIdx.x * BN;

    float acc[4][8][4];
#pragma unroll
    for (int i = 0; i < 4; i++)
#pragma unroll
        for (int j = 0; j < 8; j++)
#pragma unroll
            for (int q = 0; q < 4; q++) acc[i][j][q] = 0.0f;

    const int nc = K / BK;
    const int lr = tid >> 3;            // 0..31
    const int lc = tid & 7;             // 16B col 0..7
    const float* pA = A + (size_t)(bm + lr) * K + lc * 4;
    const float* pB = Bm + (size_t)(bn + lr) * K + lc * 4;
    const uint32_t dsto = lr * (TRS * 4) + lc * 16;

    auto load_chunk = [&](int c, int stg) {
        const uint32_t db = sbase + stg * STAGE;
        const size_t ko = (size_t)c * BK;
#pragma unroll
        for (int wv = 0; wv < 4; wv++)
            CP_ASYNC16(db + dsto + wv * (32 * TRS * 4), pA + (size_t)wv * 32 * K + ko);
#pragma unroll
        for (int wv = 0; wv < 8; wv++)
            CP_ASYNC16(db + SA_BYTES + dsto + wv * (32 * TRS * 4),
                       pB + (size_t)wv * 32 * K + ko);
        CP_COMMIT();
    };

    load_chunk(0, 0);
    if (nc > 1) load_chunk(1, 1);

    const int g = lane >> 2;            // 0..7
    const int l4 = lane & 3;            // 0..3

    for (int c = 0; c < nc; c++) {
        const int stg = c % NSTAGE;
        if (c + 1 < nc) CP_WAIT1(); else CP_WAIT0();
        __syncthreads();                // publishes chunk c; frees stage (c+2)%3
        if (c + 2 < nc) load_chunk(c + 2, (c + 2) % NSTAGE);

        const uint32_t sA = sbase + stg * STAGE;
        const uint32_t sB = sA + SA_BYTES;
#pragma unroll
        for (int kk = 0; kk < 4; kk++) {
            const uint32_t kof = (kk * 8 + 2 * l4) * 4;
            uint32_t bf[8][2];
#pragma unroll
            for (int nt = 0; nt < 8; nt++)
                LDS64(bf[nt][0], bf[nt][1], sB + (warp_n + nt * 8 + g) * (TRS * 4) + kof);
#pragma unroll
            for (int mt = 0; mt < 4; mt++) {
                int m = warp_m + mt * 16 + g;
                uint32_t a0, a2, a1, a3;
                LDS64(a0, a2, sA + m * (TRS * 4) + kof);
                LDS64(a1, a3, sA + (m + 8) * (TRS * 4) + kof);
#pragma unroll
                for (int nt = 0; nt < 8; nt++)
                    MMATF32(acc[mt][nt], a0, a1, a2, a3, bf[nt][0], bf[nt][1]);
            }
        }
    }

    // epilogue
    const int q2 = l4 * 2;
#pragma unroll
    for (int mt = 0; mt < 4; mt++) {
#pragma unroll
        for (int half = 0; half < 2; half++) {
            int row = bm + warp_m + mt * 16 + g + half * 8;
#pragma unroll
            for (int nt = 0; nt < 8; nt++) {
                int col = bn + warp_n + nt * 8 + q2;
                float v0 = acc[mt][nt][half * 2 + 0] + __ldg(&bias[col + 0]);
                float v1 = acc[mt][nt][half * 2 + 1] + __ldg(&bias[col + 1]);
                if (mode == 0) {
                    float2 o; o.x = v0; o.y = v1;
                    *(float2*)&Cf[(size_t)row * N + col] = o;
                } else {
                    Cf[(size_t)row * N + kperm(col)] = tf32r(gelu_exact(v0));
                    Cf[(size_t)row * N + kperm(col + 1)] = tf32r(gelu_exact(v1));
                }
            }
        }
    }
}

// ---------------------------------------------------------------------------
// PE add: x = ff + PE (exact fp32) and xt (tf32 + K-permuted)
// ---------------------------------------------------------------------------
__global__ void pe_add_kernel(const float* __restrict__ ff,
                              const int* __restrict__ idx32,
                              float* __restrict__ x,
                              float* __restrict__ xt) {
    int p = blockIdx.x * blockDim.x + threadIdx.x;
    int tok = p >> 9;
    int d = (p & 511) << 1;
    bool is64 = (idx32[1] == 0);
    float pos = (float)(is64 ? idx32[2 * tok] : idx32[tok]);
    float ang = pos * expf(-9.210340371976184f * (float)d / (float)DD);
    float s, c;
    sincosf(ang, &s, &c);
    size_t i = (size_t)p * 2;
    float2 f = *(const float2*)&ff[i];
    float v0 = f.x + s;
    float v1 = f.y + c;
    *(float2*)&x[i] = make_float2(v0, v1);
    size_t rb = (size_t)tok * DD;
    xt[rb + kperm(d)] = tf32r(v0);
    xt[rb + kperm(d + 1)] = tf32r(v1);
}

// ---------------------------------------------------------------------------
// Weight round + permute
// ---------------------------------------------------------------------------
__global__ void round_perm_kernel(const float* __restrict__ in,
                                  float* __restrict__ out, int n4) {
    int i = blockIdx.x * blockDim.x + threadIdx.x;
    if (i < n4) {
        size_t b = (size_t)i * 4;
        float4 v = *(const float4*)&in[b];
        size_t base = (b & ~(size_t)7) + ((b & 4) ? 1 : 0);
        out[base + 0] = tf32r(v.x);
        out[base + 2] = tf32r(v.y);
        out[base + 4] = tf32r(v.z);
        out[base + 6] = tf32r(v.w);
    }
}

// ---------------------------------------------------------------------------
// Per-window attention (fp32) -> aot (tf32 + K-permuted)
// ---------------------------------------------------------------------------
__global__ __launch_bounds__(256)
void attn_win_kernel(const float* __restrict__ qkv, float* __restrict__ aot) {
    __shared__ float q[16][132];
    __shared__ float k[16][132];
    __shared__ float v[16][132];
    __shared__ float s[16][16];

    const int h = blockIdx.x;
    const int n = blockIdx.y;
    const int b = blockIdx.z;
    const int tid = threadIdx.x;

    const long base = ((long)b * TT + (long)n * WW) * D3;
    const int qo = h * HDIM;
    const int ko = DD + h * HDIM;
    const int vo = 2 * DD + h * HDIM;

#pragma unroll
    for (int i = 0; i < 8; i++) {
        int e = tid + i * 256;
        int r = e >> 7;
        int d = e & 127;
        long rb = base + (long)r * D3;
        q[r][d] = qkv[rb + qo + d];
        k[r][d] = qkv[rb + ko + d];
        v[r][d] = qkv[rb + vo + d];
    }
    __syncthreads();

    {
        int qi = tid >> 4, ki = tid & 15;
        float acc = 0.0f;
#pragma unroll
        for (int d4 = 0; d4 < 32; d4++) {
            float4 qq = *(const float4*)&q[qi][d4 * 4];
            float4 kk = *(const float4*)&k[ki][d4 * 4];
            acc += qq.x * kk.x + qq.y * kk.y + qq.z * kk.z + qq.w * kk.w;
        }
        s[qi][ki] = acc * 0.08838834764831845f;
    }
    __syncthreads();

    if (tid < 16) {
        float mx = -1e30f;
#pragma unroll
        for (int j = 0; j < 16; j++) mx = fmaxf(mx, s[tid][j]);
        float p[16];
        float sum = 0.0f;
#pragma unroll
        for (int j = 0; j < 16; j++) { p[j] = expf(s[tid][j] - mx); sum += p[j]; }
        float inv = 1.0f / sum;
#pragma unroll
        for (int j = 0; j < 16; j++) s[tid][j] = p[j] * inv;
    }
    __syncthreads();

    const long obase = ((long)b * TT + (long)n * WW) * DD;
#pragma unroll
    for (int i = 0; i < 8; i++) {
        int e = tid + i * 256;
        int r = e >> 7;
        int d = e & 127;
        float acc = 0.0f;
#pragma unroll
        for (int j = 0; j < 16; j++) acc += s[r][j] * v[j][d];
        aot[obase + (long)r * DD + h * HDIM + kperm(d)] = tf32r(acc);
    }
}

// ---------------------------------------------------------------------------
// LayerNorm(a + b); optionally emits tf32+K-permuted copy
// ---------------------------------------------------------------------------
__device__ __forceinline__ float warp_sum(float x) {
#pragma unroll
    for (int off = 16; off > 0; off >>= 1) x += __shfl_xor_sync(0xffffffffu, x, off);
    return x;
}

__global__ __launch_bounds__(256)
void ln_add_kernel(const float* __restrict__ a, const float* __restrict__ bres,
                   const float* __restrict__ g, const float* __restrict__ beta,
                   float* __restrict__ out, float* __restrict__ ot) {
    __shared__ float rs[8], rq[8], tot[2];
    const int row = blockIdx.x;
    const int tid = threadIdx.x;
    const long rb = (long)row * DD;

    float vals[4];
    float s = 0.0f, sq = 0.0f;
#pragma unroll
    for (int i = 0; i < 4; i++) {
        int c = tid + i * 256;
        float x = a[rb + c] + bres[rb + c];
        vals[i] = x;
        s += x;
        sq += x * x;
    }
    float ws = warp_sum(s), wq = warp_sum(sq);
    int wid = tid >> 5, lane = tid & 31;
    if (lane == 0) { rs[wid] = ws; rq[wid] = wq; }
    __syncthreads();
    if (tid == 0) {
        float ta = 0.0f, tb = 0.0f;
#pragma unroll
        for (int i = 0; i < 8; i++) { ta += rs[i]; tb += rq[i]; }
        tot[0] = ta; tot[1] = tb;
    }
    __syncthreads();
    float mean = tot[0] * (1.0f / DD);
    float var = tot[1] * (1.0f / DD) - mean * mean;
    float inv = rsqrtf(var + 1e-5f);
#pragma unroll
    for (int i = 0; i < 4; i++) {
        int c = tid + i * 256;
        float o = (vals[i] - mean) * inv * g[c] + beta[c];
        out[rb + c] = o;
        if (ot) ot[rb + kperm(c)] = tf32r(o);
    }
}

// ---------------------------------------------------------------------------
// Launch
// ---------------------------------------------------------------------------
extern "C" void kernel_launch(void* const* d_in, const int* in_sizes, int n_in,
                              void* d_out, int out_size) {
    const float* ff    = (const float*)d_in[0];
    const int*   fi    = (const int*)d_in[1];
    const float* w_qkv = (const float*)d_in[2];
    const float* b_qkv = (const float*)d_in[3];
    const float* w_out = (const float*)d_in[4];
    const float* b_out = (const float*)d_in[5];
    const float* w1    = (const float*)d_in[6];
    const float* b1    = (const float*)d_in[7];
    const float* w2    = (const float*)d_in[8];
    const float* b2    = (const float*)d_in[9];
    const float* g1    = (const float*)d_in[10];
    const float* bet1  = (const float*)d_in[11];
    const float* g2    = (const float*)d_in[12];
    const float* bet2  = (const float*)d_in[13];
    float* out         = (float*)d_out;

    float *px, *pxt, *pqkv, *paot, *pproj, *ph, *pht, *pf1t, *pf2;
    float *pwqkvt, *pwoutt, *pw1t, *pw2t;
    cudaGetSymbolAddress((void**)&px, g_x);
    cudaGetSymbolAddress((void**)&pxt, g_xt);
    cudaGetSymbolAddress((void**)&pqkv, g_qkv);
    cudaGetSymbolAddress((void**)&paot, g_aot);
    cudaGetSymbolAddress((void**)&pproj, g_proj);
    cudaGetSymbolAddress((void**)&ph, g_h);
    cudaGetSymbolAddress((void**)&pht, g_ht);
    cudaGetSymbolAddress((void**)&pf1t, g_f1t);
    cudaGetSymbolAddress((void**)&pf2, g_f2);
    cudaGetSymbolAddress((void**)&pwqkvt, g_wqkvt);
    cudaGetSymbolAddress((void**)&pwoutt, g_woutt);
    cudaGetSymbolAddress((void**)&pw1t, g_w1t);
    cudaGetSymbolAddress((void**)&pw2t, g_w2t);

    cudaFuncSetAttribute(gemm_tf32, cudaFuncAttributeMaxDynamicSharedMemorySize, TGSMEM);

    // weight prep (round + permute)
    round_perm_kernel<<<(D3 * DD / 4 + 255) / 256, 256>>>(w_qkv, pwqkvt, D3 * DD / 4);
    round_perm_kernel<<<(DD * DD / 4 + 255) / 256, 256>>>(w_out, pwoutt, DD * DD / 4);
    round_perm_kernel<<<(D4 * DD / 4 + 255) / 256, 256>>>(w1, pw1t, D4 * DD / 4);
    round_perm_kernel<<<(DD * D4 / 4 + 255) / 256, 256>>>(w2, pw2t, DD * D4 / 4);

    // 1) PE add -> x (exact) + xt (tf32 perm)
    pe_add_kernel<<<(MTOK * DD / 2) / 256, 256>>>(ff, fi, px, pxt);

    // 2) QKV projection (tf32) -> fp32 qkv
    gemm_tf32<<<dim3(D3 / BN, MTOK / BM), 256, TGSMEM>>>(
        pxt, pwqkvt, b_qkv, pqkv, D3, DD, 0);

    // 3) windowed attention -> aot (tf32 perm)
    attn_win_kernel<<<dim3(HH, NWIN, BB), 256>>>(pqkv, paot);

    // 4) out projection (tf32) -> fp32 proj
    gemm_tf32<<<dim3(DD / BN, MTOK / BM), 256, TGSMEM>>>(
        paot, pwoutt, b_out, pproj, DD, DD, 0);

    // 5) LN1(x + proj) -> h (exact) + ht (tf32 perm)
    ln_add_kernel<<<MTOK, 256>>>(px, pproj, g1, bet1, ph, pht);

    // 6) FFN1 + GELU (tf32) -> f1t (tf32 perm)
    gemm_tf32<<<dim3(D4 / BN, MTOK / BM), 256, TGSMEM>>>(
        pht, pw1t, b1, pf1t, D4, DD, 1);

    // 7) FFN2 (tf32) -> f2 fp32
    gemm_tf32<<<dim3(DD / BN, MTOK / BM), 256, TGSMEM>>>(
        pf1t, pw2t, b2, pf2, DD, D4, 0);

    // 8) LN2(h + f2) -> out
    ln_add_kernel<<<MTOK, 256>>>(ph, pf2, g2, bet2, out, nullptr);
}